// round 1
// baseline (speedup 1.0000x reference)
#include <cuda_runtime.h>

#define NN 128
#define PITCH 132          // 132 % 32 == 4 -> conflict-free columns; 132*4B = 16B-aligned rows
#define THREADS 256
#define SMEM_FLOATS (NN*PITCH + 5*NN + 3*NN)   // A + kx,ky,kz,cw,sw + rs rows
#define SMEM_BYTES (SMEM_FLOATS * sizeof(float))

__global__ void __launch_bounds__(THREADS)
lsd_kernel(const float* __restrict__ rs,
           const float* __restrict__ kp,
           const float* __restrict__ cw,
           const float* __restrict__ sw,
           float* __restrict__ out)
{
    extern __shared__ float smem[];
    float* A   = smem;                 // NN * PITCH
    float* kx  = smem + NN * PITCH;    // NN
    float* ky  = kx + NN;
    float* kz  = ky + NN;
    float* scw = kz + NN;
    float* ssw = scw + NN;
    float* sr  = ssw + NN;             // 3*NN

    __shared__ unsigned skeys[4];
    __shared__ int s_p;
    __shared__ float s_rpiv;

    const int tid = threadIdx.x;
    const int b = blockIdx.x;

    if (tid < NN) {
        kx[tid]  = kp[3 * tid + 0];
        ky[tid]  = kp[3 * tid + 1];
        kz[tid]  = kp[3 * tid + 2];
        scw[tid] = cw[tid];
        ssw[tid] = sw[tid];
    }
    const float* rsb = rs + (size_t)b * (3 * NN);
    for (int t = tid; t < 3 * NN; t += THREADS) sr[t] = rsb[t];
    __syncthreads();

    // Build Slater matrix: A[i][m] = cw[m]*cos(k_m . r_i) - sw[m]*sin(k_m . r_i)
    for (int idx = tid; idx < NN * NN; idx += THREADS) {
        const int i = idx >> 7;
        const int m = idx & 127;
        float d = fmaf(sr[3 * i], kx[m],
                  fmaf(sr[3 * i + 1], ky[m], sr[3 * i + 2] * kz[m]));
        float s, c;
        __sincosf(d, &s, &c);
        A[i * PITCH + m] = scw[m] * c - ssw[m] * s;
    }
    __syncthreads();

    float acc = 0.0f;   // thread 0 accumulates log|det|

    for (int k = 0; k < NN; ++k) {
        // ---- partial-pivot search on column k (rows >= k) ----
        if (tid < NN) {
            unsigned key = 0u;
            if (tid >= k) {
                float v = fabsf(A[tid * PITCH + k]);
                // non-negative float bits are order-preserving; pack row in low 7 bits
                key = (__float_as_uint(v) & 0xFFFFFF80u) | (unsigned)tid;
            }
            unsigned wmax = __reduce_max_sync(0xFFFFFFFFu, key);
            if ((tid & 31) == 0) skeys[tid >> 5] = wmax;
        }
        __syncthreads();
        if (tid == 0) {
            unsigned m01 = skeys[0] > skeys[1] ? skeys[0] : skeys[1];
            unsigned m23 = skeys[2] > skeys[3] ? skeys[2] : skeys[3];
            unsigned mm  = m01 > m23 ? m01 : m23;
            const int p = (int)(mm & 127u);
            const float piv = A[p * PITCH + k];
            s_p = p;
            s_rpiv = 1.0f / piv;
            acc += __logf(fabsf(piv));
        }
        __syncthreads();
        const int p = s_p;
        const float rpiv = s_rpiv;

        // ---- row swap (block-uniform branch) ----
        if (p != k) {
            if (tid < NN) {
                const float t0 = A[k * PITCH + tid];
                A[k * PITCH + tid] = A[p * PITCH + tid];
                A[p * PITCH + tid] = t0;
            }
            __syncthreads();
        }

        // ---- rank-1 trailing update: 2 threads per row, float4 quads ----
        if (k < NN - 1) {
            const int i = tid & 127;
            const int h = tid >> 7;
            if (i > k) {
                const float lv = A[i * PITCH + k] * rpiv;
                const int jstart = k + 1;
                const int q0 = (jstart + 3) >> 2;     // first full quad
                if (h == 0) {
                    for (int j = jstart; j < (q0 << 2); ++j)
                        A[i * PITCH + j] = fmaf(-lv, A[k * PITCH + j], A[i * PITCH + j]);
                }
                const float4* Uk = (const float4*)(A + k * PITCH);
                float4* Ai = (float4*)(A + i * PITCH);
                #pragma unroll 2
                for (int q = q0 + h; q < 32; q += 2) {
                    float4 u = Uk[q];
                    float4 a = Ai[q];
                    a.x = fmaf(-lv, u.x, a.x);
                    a.y = fmaf(-lv, u.y, a.y);
                    a.z = fmaf(-lv, u.z, a.z);
                    a.w = fmaf(-lv, u.w, a.w);
                    Ai[q] = a;
                }
            }
        }
        __syncthreads();
    }

    if (tid == 0) out[b] = acc;
}

extern "C" void kernel_launch(void* const* d_in, const int* in_sizes, int n_in,
                              void* d_out, int out_size)
{
    const float* rs = (const float*)d_in[0];
    const float* kp = (const float*)d_in[1];
    const float* cw = (const float*)d_in[2];
    const float* sw = (const float*)d_in[3];
    float* out = (float*)d_out;

    const int batch = in_sizes[0] / (3 * NN);

    cudaFuncSetAttribute(lsd_kernel,
                         cudaFuncAttributeMaxDynamicSharedMemorySize,
                         (int)SMEM_BYTES);

    lsd_kernel<<<batch, THREADS, SMEM_BYTES>>>(rs, kp, cw, sw, out);
}

// round 2
// speedup vs baseline: 1.5270x; 1.5270x over previous
#include <cuda_runtime.h>

#define NN 128
#define PITCH 132          // rows 16B-aligned (132*4B=528, 528%16==0) -> float4 row ops
#define NB 8               // panel width; NN/NB = 16 block steps
#define THREADS 256
// A (NN*PITCH) + kx,ky,kz,cw,sw (5*NN) + rs rows (3*NN, later aliased as pivot store)
#define SMEM_FLOATS (NN*PITCH + 5*NN + 3*NN)
#define SMEM_BYTES (SMEM_FLOATS * sizeof(float))

__global__ void __launch_bounds__(THREADS, 3)
lsd_kernel(const float* __restrict__ rs,
           const float* __restrict__ kp,
           const float* __restrict__ cw,
           const float* __restrict__ sw,
           float* __restrict__ out)
{
    extern __shared__ float smem[];
    float* A   = smem;                 // NN * PITCH
    float* kx  = smem + NN * PITCH;    // NN
    float* ky  = kx + NN;
    float* kz  = ky + NN;
    float* scw = kz + NN;
    float* ssw = scw + NN;
    float* sr  = ssw + NN;             // 3*NN (dead after build; reused as spiv)
    float* spiv = sr;                  // NN pivot values (alias)

    __shared__ int s_p;
    __shared__ float s_rpiv;
    __shared__ float s_part[4];

    const int tid = threadIdx.x;
    const int b = blockIdx.x;

    if (tid < NN) {
        kx[tid]  = kp[3 * tid + 0];
        ky[tid]  = kp[3 * tid + 1];
        kz[tid]  = kp[3 * tid + 2];
        scw[tid] = cw[tid];
        ssw[tid] = sw[tid];
    }
    const float* rsb = rs + (size_t)b * (3 * NN);
    for (int t = tid; t < 3 * NN; t += THREADS) sr[t] = rsb[t];
    __syncthreads();

    // Build Slater matrix: A[i][m] = cw[m]*cos(k_m . r_i) - sw[m]*sin(k_m . r_i)
    // (read sr before overwriting: each thread's reads precede any spiv write
    //  because spiv writes only happen in the LU phase after a barrier)
    for (int idx = tid; idx < NN * NN; idx += THREADS) {
        const int i = idx >> 7;
        const int m = idx & 127;
        float d = fmaf(sr[3 * i], kx[m],
                  fmaf(sr[3 * i + 1], ky[m], sr[3 * i + 2] * kz[m]));
        float s, c;
        __sincosf(d, &s, &c);
        A[i * PITCH + m] = scw[m] * c - ssw[m] * s;
    }
    __syncthreads();

    // ================= Blocked LU with partial pivoting =================
    for (int kb = 0; kb < NN; kb += NB) {

        // ---- panel factorization: columns kb .. kb+NB-1 ----
        #pragma unroll 1
        for (int kk = 0; kk < NB; ++kk) {
            const int k = kb + kk;

            // pivot search on column k (rows >= k), warp 0 only
            if (tid < 32) {
                unsigned key = 0u;
                #pragma unroll
                for (int w = 0; w < 4; ++w) {
                    const int i = tid + 32 * w;
                    if (i >= k) {
                        const float v = fabsf(A[i * PITCH + k]);
                        const unsigned kv =
                            (__float_as_uint(v) & 0xFFFFFF80u) | (unsigned)i;
                        key = key > kv ? key : kv;
                    }
                }
                const unsigned mm = __reduce_max_sync(0xFFFFFFFFu, key);
                if (tid == 0) {
                    const int p = (int)(mm & 127u);
                    const float piv = A[p * PITCH + k];
                    s_p = p;
                    s_rpiv = 1.0f / piv;
                    spiv[k] = piv;
                }
            }
            __syncthreads();
            const int p = s_p;
            const float rpiv = s_rpiv;

            // full-width row swap (block-uniform branch)
            if (p != k) {
                if (tid < NN) {
                    const float t0 = A[k * PITCH + tid];
                    A[k * PITCH + tid] = A[p * PITCH + tid];
                    A[p * PITCH + tid] = t0;
                }
                __syncthreads();
            }

            // scale column k (store L multipliers) + update remaining panel cols
            if (tid < NN && tid > k) {
                const int i = tid;
                const float l = A[i * PITCH + k] * rpiv;
                A[i * PITCH + k] = l;
                #pragma unroll
                for (int j = k + 1; j < kb + NB; ++j)
                    A[i * PITCH + j] = fmaf(-l, A[k * PITCH + j], A[i * PITCH + j]);
            }
            __syncthreads();
        }

        const int c0 = kb + NB;        // trailing start (multiple of 8)
        const int M = NN - c0;
        if (M > 0) {
            // ---- TRSM: U12 = L11^{-1} * A12, one thread per column ----
            {
                const int j = c0 + tid;
                if (j < NN) {
                    float v[NB];
                    #pragma unroll
                    for (int m = 0; m < NB; ++m)
                        v[m] = A[(kb + m) * PITCH + j];
                    #pragma unroll
                    for (int m = 1; m < NB; ++m) {
                        #pragma unroll
                        for (int n = 0; n < m; ++n)
                            v[m] = fmaf(-A[(kb + m) * PITCH + (kb + n)], v[n], v[m]);
                    }
                    #pragma unroll
                    for (int m = 0; m < NB; ++m)
                        A[(kb + m) * PITCH + j] = v[m];
                }
            }
            __syncthreads();

            // ---- trailing GEMM: A22 -= L21 * U12 (register-blocked) ----
            const int q0 = c0 >> 2;        // first trailing quad
            const int Q = 32 - q0;         // number of trailing quads (= M/4)
            const int rgroup = tid >> 5;   // 0..7 (warp id): all lanes share row
            const int qlane = tid & 31;
            if (qlane < Q) {
                const int q = q0 + qlane;
                float4 u[NB];
                #pragma unroll
                for (int m = 0; m < NB; ++m)
                    u[m] = *(const float4*)(A + (kb + m) * PITCH + 4 * q);

                for (int i = c0 + rgroup; i < NN; i += 8) {
                    float* Arow = A + i * PITCH;
                    // L row segment: broadcast across the warp (all lanes same i)
                    const float4 l0 = *(const float4*)(Arow + kb);
                    const float4 l1 = *(const float4*)(Arow + kb + 4);
                    float4 a = *(float4*)(Arow + 4 * q);
                    const float lm[NB] = {l0.x, l0.y, l0.z, l0.w,
                                          l1.x, l1.y, l1.z, l1.w};
                    #pragma unroll
                    for (int m = 0; m < NB; ++m) {
                        a.x = fmaf(-lm[m], u[m].x, a.x);
                        a.y = fmaf(-lm[m], u[m].y, a.y);
                        a.z = fmaf(-lm[m], u[m].z, a.z);
                        a.w = fmaf(-lm[m], u[m].w, a.w);
                    }
                    *(float4*)(Arow + 4 * q) = a;
                }
            }
            __syncthreads();
        }
    }

    // ---- log|det| = sum log|piv| (parallel, deferred) ----
    float lv = 0.0f;
    if (tid < NN) lv = __logf(fabsf(spiv[tid]));
    #pragma unroll
    for (int o = 16; o > 0; o >>= 1)
        lv += __shfl_xor_sync(0xFFFFFFFFu, lv, o);
    if (tid < NN && (tid & 31) == 0) s_part[tid >> 5] = lv;
    __syncthreads();
    if (tid == 0)
        out[b] = s_part[0] + s_part[1] + s_part[2] + s_part[3];
}

extern "C" void kernel_launch(void* const* d_in, const int* in_sizes, int n_in,
                              void* d_out, int out_size)
{
    const float* rs = (const float*)d_in[0];
    const float* kp = (const float*)d_in[1];
    const float* cw = (const float*)d_in[2];
    const float* sw = (const float*)d_in[3];
    float* out = (float*)d_out;

    const int batch = in_sizes[0] / (3 * NN);

    cudaFuncSetAttribute(lsd_kernel,
                         cudaFuncAttributeMaxDynamicSharedMemorySize,
                         (int)SMEM_BYTES);

    lsd_kernel<<<batch, THREADS, SMEM_BYTES>>>(rs, kp, cw, sw, out);
}

// round 3
// speedup vs baseline: 2.2742x; 1.4894x over previous
#include <cuda_runtime.h>

#define NN 128
#define PITCH 132          // rows 16B-aligned -> float4 row ops
#define NB 8               // panel width; NN/NB = 16 block steps
#define THREADS 256
#define SMEM_FLOATS (NN*PITCH + 8*NN)
#define SMEM_BYTES (SMEM_FLOATS * sizeof(float))

__global__ void __launch_bounds__(THREADS, 3)
lsd_kernel(const float* __restrict__ rs,
           const float* __restrict__ kp,
           const float* __restrict__ cw,
           const float* __restrict__ sw,
           float* __restrict__ out)
{
    extern __shared__ float smem[];
    float* A   = smem;                 // NN * PITCH
    float* kx  = smem + NN * PITCH;    // NN   (build only)
    float* ky  = kx + NN;              // NN   (build only)
    float* kz  = ky + NN;
    float* scw = kz + NN;
    float* ssw = scw + NN;
    float* sr  = ssw + NN;             // 3*NN (build only)
    // aliases (dead after build):
    float* spiv = kx;                  // NN pivot values
    int*   list = (int*)ky;            // NN active-row list

    __shared__ int s_pivrow[NB];
    __shared__ unsigned s_chosen[4];
    __shared__ int s_nact;
    __shared__ float s_part[4];

    const int tid = threadIdx.x;
    const int b = blockIdx.x;
    const unsigned FULL = 0xFFFFFFFFu;

    if (tid < NN) {
        kx[tid]  = kp[3 * tid + 0];
        ky[tid]  = kp[3 * tid + 1];
        kz[tid]  = kp[3 * tid + 2];
        scw[tid] = cw[tid];
        ssw[tid] = sw[tid];
    }
    const float* rsb = rs + (size_t)b * (3 * NN);
    for (int t = tid; t < 3 * NN; t += THREADS) sr[t] = rsb[t];
    __syncthreads();

    // Build Slater matrix: A[i][m] = cw[m]*cos(k_m . r_i) - sw[m]*sin(k_m . r_i)
    for (int idx = tid; idx < NN * NN; idx += THREADS) {
        const int i = idx >> 7;
        const int m = idx & 127;
        float d = fmaf(sr[3 * i], kx[m],
                  fmaf(sr[3 * i + 1], ky[m], sr[3 * i + 2] * kz[m]));
        float s, c;
        __sincosf(d, &s, &c);
        A[i * PITCH + m] = scw[m] * c - ssw[m] * s;
    }
    __syncthreads();

    if (tid < 4) s_chosen[tid] = 0u;
    __syncthreads();

    // ============ Blocked LU, pivot-flag form (no row swaps) ============
    for (int kb = 0; kb < NN; kb += NB) {

        // ---- panel factorization: warp 0, registers only ----
        if (tid < 32) {
            float pr[4][NB];
            unsigned act = 0u;
            #pragma unroll
            for (int s2 = 0; s2 < 4; ++s2) {
                const float* row = A + (unsigned)(tid + 32 * s2) * PITCH + kb;
                const float4 a0 = *(const float4*)row;
                const float4 a1 = *(const float4*)(row + 4);
                pr[s2][0] = a0.x; pr[s2][1] = a0.y; pr[s2][2] = a0.z; pr[s2][3] = a0.w;
                pr[s2][4] = a1.x; pr[s2][5] = a1.y; pr[s2][6] = a1.z; pr[s2][7] = a1.w;
                act |= ((~s_chosen[s2] >> tid) & 1u) << s2;
            }

            #pragma unroll
            for (int kk = 0; kk < NB; ++kk) {
                // pivot search over active rows (float bits order-preserving)
                unsigned key = 0u;
                #pragma unroll
                for (int s2 = 0; s2 < 4; ++s2) {
                    if ((act >> s2) & 1u) {
                        const unsigned kv =
                            (__float_as_uint(fabsf(pr[s2][kk])) & 0xFFFFFF80u)
                            | (unsigned)(tid + 32 * s2);
                        key = key > kv ? key : kv;
                    }
                }
                const unsigned mm = __reduce_max_sync(FULL, key);
                const int p = (int)(mm & 127u);
                const int plane = p & 31;
                const int pslot = p >> 5;

                // broadcast pivot row cols kk..NB-1 (pslot uniform -> SELs)
                float up[NB];
                #pragma unroll
                for (int j = kk; j < NB; ++j) {
                    const float t = pslot == 0 ? pr[0][j]
                                  : pslot == 1 ? pr[1][j]
                                  : pslot == 2 ? pr[2][j] : pr[3][j];
                    up[j] = __shfl_sync(FULL, t, plane);
                }
                const float pv = up[kk];
                const float rp = __fdividef(1.0f, pv);

                if (tid == plane) act &= ~(1u << pslot);   // retire pivot row
                if (tid == 0) { s_pivrow[kk] = p; spiv[kb + kk] = pv; }

                #pragma unroll
                for (int s2 = 0; s2 < 4; ++s2) {
                    if ((act >> s2) & 1u) {
                        const float l = pr[s2][kk] * rp;
                        pr[s2][kk] = l;
                        #pragma unroll
                        for (int j = kk + 1; j < NB; ++j)
                            pr[s2][j] = fmaf(-l, up[j], pr[s2][j]);
                    }
                }
            }

            // write back panel
            #pragma unroll
            for (int s2 = 0; s2 < 4; ++s2) {
                float* row = A + (unsigned)(tid + 32 * s2) * PITCH + kb;
                *(float4*)row =
                    make_float4(pr[s2][0], pr[s2][1], pr[s2][2], pr[s2][3]);
                *(float4*)(row + 4) =
                    make_float4(pr[s2][4], pr[s2][5], pr[s2][6], pr[s2][7]);
            }

            // update chosen mask + ballot-compact active list
            int base = 0;
            #pragma unroll
            for (int s2 = 0; s2 < 4; ++s2) {
                const unsigned am = __ballot_sync(FULL, (act >> s2) & 1u);
                if (tid == 0) s_chosen[s2] = ~am;
                const int pos = base + __popc(am & ((1u << tid) - 1u));
                if ((act >> s2) & 1u) list[pos] = tid + 32 * s2;
                base += __popc(am);
            }
            if (tid == 0) s_nact = base;
        }
        __syncthreads();

        const int c0 = kb + NB;
        if (c0 < NN) {
            // ---- TRSM: U12 rows = scattered pivot rows ----
            {
                const int j = c0 + tid;
                if (j < NN) {
                    int prw[NB];
                    #pragma unroll
                    for (int m = 0; m < NB; ++m) prw[m] = s_pivrow[m];
                    float l11[NB][NB];
                    #pragma unroll
                    for (int m = 1; m < NB; ++m)
                        #pragma unroll
                        for (int n = 0; n < m; ++n)
                            l11[m][n] = A[prw[m] * PITCH + kb + n]; // broadcast
                    float v[NB];
                    #pragma unroll
                    for (int m = 0; m < NB; ++m)
                        v[m] = A[prw[m] * PITCH + j];
                    #pragma unroll
                    for (int m = 1; m < NB; ++m)
                        #pragma unroll
                        for (int n = 0; n < m; ++n)
                            v[m] = fmaf(-l11[m][n], v[n], v[m]);
                    #pragma unroll
                    for (int m = 0; m < NB; ++m)
                        A[prw[m] * PITCH + j] = v[m];
                }
            }
            __syncthreads();

            // ---- GEMM: active rows -= L21 * U12 (register-blocked) ----
            const int q0v = c0 >> 2;
            const int Q = 32 - q0v;
            const int rg = tid >> 5;
            const int ql = tid & 31;
            if (ql < Q) {
                const int q = q0v + ql;
                float4 u[NB];
                #pragma unroll
                for (int m = 0; m < NB; ++m)
                    u[m] = *(const float4*)(A + s_pivrow[m] * PITCH + 4 * q);
                const int nact = s_nact;
                #pragma unroll 2
                for (int idx = rg; idx < nact; idx += 8) {
                    float* Arow = A + (unsigned)list[idx] * PITCH; // broadcast
                    const float4 l0 = *(const float4*)(Arow + kb);
                    const float4 l1 = *(const float4*)(Arow + kb + 4);
                    float4 a = *(float4*)(Arow + 4 * q);
                    const float lm[NB] = {l0.x, l0.y, l0.z, l0.w,
                                          l1.x, l1.y, l1.z, l1.w};
                    #pragma unroll
                    for (int m = 0; m < NB; ++m) {
                        a.x = fmaf(-lm[m], u[m].x, a.x);
                        a.y = fmaf(-lm[m], u[m].y, a.y);
                        a.z = fmaf(-lm[m], u[m].z, a.z);
                        a.w = fmaf(-lm[m], u[m].w, a.w);
                    }
                    *(float4*)(Arow + 4 * q) = a;
                }
            }
        }
        __syncthreads();
    }

    // ---- log|det| = sum log|piv| ----
    float lv = 0.0f;
    if (tid < NN) lv = __logf(fabsf(spiv[tid]));
    #pragma unroll
    for (int o = 16; o > 0; o >>= 1)
        lv += __shfl_xor_sync(FULL, lv, o);
    if (tid < NN && (tid & 31) == 0) s_part[tid >> 5] = lv;
    __syncthreads();
    if (tid == 0)
        out[b] = s_part[0] + s_part[1] + s_part[2] + s_part[3];
}

extern "C" void kernel_launch(void* const* d_in, const int* in_sizes, int n_in,
                              void* d_out, int out_size)
{
    const float* rs = (const float*)d_in[0];
    const float* kp = (const float*)d_in[1];
    const float* cw = (const float*)d_in[2];
    const float* sw = (const float*)d_in[3];
    float* out = (float*)d_out;

    const int batch = in_sizes[0] / (3 * NN);

    cudaFuncSetAttribute(lsd_kernel,
                         cudaFuncAttributeMaxDynamicSharedMemorySize,
                         (int)SMEM_BYTES);

    lsd_kernel<<<batch, THREADS, SMEM_BYTES>>>(rs, kp, cw, sw, out);
}